// round 6
// baseline (speedup 1.0000x reference)
#include <cuda_runtime.h>
#include <cstdint>
#include <cstddef>

// CustomConv 3x3 s1 p1: NHWC(32,56,56,128) x HWIO(3,3,128,256) + bias + ReLU.
// Implicit GEMM on mma.sync m16n8k8 tf32 (legacy tensor path; tcgen05 PTX is
// rejected because the harness compiles for compute_100, not compute_100a).
//
// Round-6: logical-k permutation so A fragments load as LDS.128.
//   Physical k-slot (ks, tig, e') holds logical k = 8*tig + 2*ks + e'.
//   A smem stays plain row-major-k (gmem copy unchanged); each thread's 8
//   A-values per row are now contiguous cols 8*tig..8*tig+7 -> 2 LDS.128/row.
//   B prepack bakes the same permutation. Per-warp/slab shared loads: 48 -> 24.

#define H_ 56
#define W_ 56
#define HW 3136
#define COUT 256
#define NSLAB 36

// Prepacked B, fragment-major; 16KB per (cout-tile, slab).
__device__ float g_Bp[2][NSLAB][4096];

static __device__ __forceinline__ uint32_t smem_u32(const void* p) {
    uint32_t a;
    asm("{ .reg .u64 t; cvta.to.shared.u64 t, %1; cvt.u32.u64 %0, t; }"
        : "=r"(a) : "l"(p));
    return a;
}
static __device__ __forceinline__ float rna_tf32(float x) {
    uint32_t r;
    asm("cvt.rna.tf32.f32 %0, %1;" : "=r"(r) : "f"(x));
    return __uint_as_float(r);
}
static __device__ __forceinline__ void cpasync16(uint32_t dst, const void* src, int sz) {
    asm volatile("cp.async.cg.shared.global [%0], [%1], 16, %2;"
                 :: "r"(dst), "l"(src), "r"(sz) : "memory");
}

#define MMA_TF32(d, a0, a1, a2, a3, b0, b1)                                        \
    asm volatile(                                                                  \
        "mma.sync.aligned.m16n8k8.row.col.f32.tf32.tf32.f32 "                      \
        "{%0,%1,%2,%3}, {%4,%5,%6,%7}, {%8,%9}, {%0,%1,%2,%3};"                    \
        : "+f"((d)[0]), "+f"((d)[1]), "+f"((d)[2]), "+f"((d)[3])                   \
        : "r"(a0), "r"(a1), "r"(a2), "r"(a3), "r"(b0), "r"(b1))

// ---------------- weight prepack (once per launch, ~1.2MB) ----------------
// Fragment-major granule (16B) index:
//   granule = wn*512 + ks*128 + idx*4 + (j ^ tig),  idx = tig*8 + g
//   element e: value = W[k = 8*tig + 2*ks + (e&1)]          <-- logical-k perm
//                      [n = wn*64 + (2*j + (e>>1))*8 + g]
__global__ void prepack_kernel(const float* __restrict__ wgt) {
    const int s  = blockIdx.x;     // slab 0..35
    const int nt = blockIdx.y;     // cout tile 0..1
    const int t  = threadIdx.x;    // 0..255
    const int f  = s >> 2;         // tap 0..8
    const int cs = s & 3;          // cin slab
    float* dst = &g_Bp[nt][s][0];
    #pragma unroll
    for (int q = 0; q < 16; ++q) {
        const int l   = t * 16 + q;
        const int e   = l & 3;
        const int j   = (l >> 2) & 3;
        const int idx = (l >> 4) & 31;
        const int ks  = (l >> 9) & 3;
        const int wn  = l >> 11;
        const int tig = idx >> 3;
        const int g   = idx & 7;
        const int k   = tig * 8 + ks * 2 + (e & 1);          // logical-k permutation
        const int n   = wn * 64 + (2 * j + (e >> 1)) * 8 + g;
        const int o   = (wn * 512 + ks * 128 + idx * 4 + (j ^ tig)) * 4 + e;
        dst[o] = rna_tf32(wgt[(size_t)(f * 128 + cs * 32 + k) * COUT + nt * 128 + n]);
    }
}

// ---------------- main kernel ----------------
// dyn smem: 3 stages x (A 16KB + B 16KB) = 98304 bytes; 2 CTAs/SM (192KB).
#define SMEM_BYTES 98304

__global__ __launch_bounds__(256, 2)
void conv_mma_tf32(const float* __restrict__ in, const float* __restrict__ bias,
                   float* __restrict__ out) {
    extern __shared__ char smem[];
    const uint32_t sb = smem_u32(smem);
    const int tid  = threadIdx.x;
    const int lane = tid & 31;
    const int wid  = tid >> 5;
    const int g    = lane >> 2;      // groupID 0..7
    const int tig  = lane & 3;       // thread-in-group
    const int wm   = wid & 3;        // warp M index -> 32 rows
    const int wn   = wid >> 2;       // warp N index -> 64 cols
    const int ntCTA   = blockIdx.x;
    const int pixBase = blockIdx.y * 128;

    // A-copy ownership: thread -> pixel row (tid>>1), half (tid&1) of 32 k-floats.
    const int rowA  = tid >> 1;
    const int halfA = tid & 1;
    const int pix = pixBase + rowA;
    const int n   = pix / HW;
    const int rm  = pix - n * HW;
    const int oh  = rm / W_;
    const int ow  = rm - oh * W_;
    const int rowSw = rowA & 7;

    float acc[2][8][4];
    #pragma unroll
    for (int mt = 0; mt < 2; ++mt)
        #pragma unroll
        for (int nt = 0; nt < 8; ++nt)
            #pragma unroll
            for (int e = 0; e < 4; ++e) acc[mt][nt][e] = 0.f;

    auto issue_copies = [&](int s, int stage) {
        const uint32_t Ab = sb + (uint32_t)stage * 32768u;
        const uint32_t Bb = Ab + 16384u;
        const int f = s >> 2, cs = s & 3;
        const int kh = f / 3, kw = f - kh * 3;
        const int ih = oh + kh - 1, iw = ow + kw - 1;
        const bool inb = (unsigned)ih < (unsigned)H_ && (unsigned)iw < (unsigned)W_;
        const float* srcA = inb
            ? in + (((size_t)(n * H_ + ih) * W_ + iw) << 7) + cs * 32 + halfA * 16
            : in;
        const int sz = inb ? 16 : 0;
        #pragma unroll
        for (int q = 0; q < 4; ++q) {
            const int j = halfA * 4 + q;
            cpasync16(Ab + (uint32_t)(rowA * 128 + ((j ^ rowSw) << 4)), srcA + q * 4, sz);
        }
        const float* srcB = &g_Bp[ntCTA][s][0] + tid * 4;
        #pragma unroll
        for (int q = 0; q < 4; ++q)
            cpasync16(Bb + (uint32_t)(tid * 16 + q * 4096), srcB + q * 1024, 16);
    };

    // Prologue: slabs 0 and 1 into stages 0 and 1.
    issue_copies(0, 0);
    asm volatile("cp.async.commit_group;" ::: "memory");
    issue_copies(1, 1);
    asm volatile("cp.async.commit_group;" ::: "memory");

    // Per-thread B fragment base (byte offset within a B buffer).
    const uint32_t bfragBase = (uint32_t)((wn * 512 + (tig * 8 + g) * 4) << 4);

    // A fragment row byte-bases: rows wm*32 + q*8 + g, q = 0..3 (q<2 -> mt0, q>=2 -> mt1).
    uint32_t aRow[4];
    #pragma unroll
    for (int q = 0; q < 4; ++q) aRow[q] = (uint32_t)((wm * 32 + q * 8 + g) * 128);

    int stage = 0;
    #pragma unroll 1
    for (int s = 0; s < NSLAB; ++s) {
        asm volatile("cp.async.wait_group 1;" ::: "memory");
        __syncthreads();

        if (s + 2 < NSLAB) {
            int st2 = stage + 2; if (st2 >= 3) st2 -= 3;
            issue_copies(s + 2, st2);
        }
        asm volatile("cp.async.commit_group;" ::: "memory");

        const char* Abuf = smem + (size_t)stage * 32768;
        const char* Bbuf = Abuf + 16384;

        #pragma unroll
        for (int h = 0; h < 2; ++h) {
            // A granule for this half: cols 8*tig + h*4 .. +3  (covers ks = 2h, 2h+1)
            const uint32_t gsel = (uint32_t)(((2 * tig + h) ^ g) << 4);
            uint4 va[4];
            #pragma unroll
            for (int q = 0; q < 4; ++q)
                va[q] = *(const uint4*)(Abuf + aRow[q] + gsel);
            const uint32_t* vp = (const uint32_t*)va;   // vp[q*4 + elem]

            #pragma unroll
            for (int kk = 0; kk < 2; ++kk) {            // ks = 2h + kk
                const int ks = 2 * h + kk;
                const int e2 = 2 * kk;                  // element pair within granule
                uint32_t b[8][2];
                #pragma unroll
                for (int j = 0; j < 4; ++j) {
                    const uint4 v = *(const uint4*)(Bbuf + bfragBase + ks * 2048
                                                    + ((j ^ tig) << 4));
                    b[2 * j][0]     = v.x;
                    b[2 * j][1]     = v.y;
                    b[2 * j + 1][0] = v.z;
                    b[2 * j + 1][1] = v.w;
                }
                #pragma unroll
                for (int mt = 0; mt < 2; ++mt) {
                    const uint32_t a0 = vp[(2 * mt) * 4 + e2];
                    const uint32_t a1 = vp[(2 * mt + 1) * 4 + e2];
                    const uint32_t a2 = vp[(2 * mt) * 4 + e2 + 1];
                    const uint32_t a3 = vp[(2 * mt + 1) * 4 + e2 + 1];
                    #pragma unroll
                    for (int nt = 0; nt < 8; ++nt)
                        MMA_TF32(acc[mt][nt], a0, a1, a2, a3, b[nt][0], b[nt][1]);
                }
            }
        }

        ++stage; if (stage >= 3) stage = 0;
    }

    // -------- epilogue: bias + ReLU, direct float2 stores --------
    #pragma unroll
    for (int nt = 0; nt < 8; ++nt) {
        const int col = ntCTA * 128 + wn * 64 + nt * 8 + tig * 2;
        const float2 bb = *(const float2*)&bias[col];
        #pragma unroll
        for (int mt = 0; mt < 2; ++mt) {
            const int r0 = pixBase + wm * 32 + mt * 16 + g;
            float2 v0, v1;
            v0.x = fmaxf(acc[mt][nt][0] + bb.x, 0.f);
            v0.y = fmaxf(acc[mt][nt][1] + bb.y, 0.f);
            v1.x = fmaxf(acc[mt][nt][2] + bb.x, 0.f);
            v1.y = fmaxf(acc[mt][nt][3] + bb.y, 0.f);
            *(float2*)&out[(size_t)r0 * COUT + col] = v0;
            *(float2*)&out[(size_t)(r0 + 8) * COUT + col] = v1;
        }
    }
}

extern "C" void kernel_launch(void* const* d_in, const int* in_sizes, int n_in,
                              void* d_out, int out_size) {
    const float* prev_a   = (const float*)d_in[0];   // [32,56,56,128]
    const float* filter_w = (const float*)d_in[1];   // [3,3,128,256]
    const float* filter_b = (const float*)d_in[2];   // [256]
    float* out = (float*)d_out;                      // [100352,256]

    prepack_kernel<<<dim3(NSLAB, 2), 256>>>(filter_w);

    cudaFuncSetAttribute(conv_mma_tf32, cudaFuncAttributeMaxDynamicSharedMemorySize,
                         SMEM_BYTES);
    conv_mma_tf32<<<dim3(2, 784), 256, SMEM_BYTES>>>(prev_a, filter_b, out);
}

// round 7
// speedup vs baseline: 1.6820x; 1.6820x over previous
#include <cuda_runtime.h>
#include <cuda_fp16.h>
#include <cstdint>
#include <cstddef>

// CustomConv 3x3 s1 p1: NHWC(32,56,56,128) x HWIO(3,3,128,256) + bias + ReLU.
// Implicit GEMM on mma.sync.m16n8k16 fp16 (fp32 accumulate). fp16 carries the
// same 10 explicit mantissa bits as tf32 but does 2x K per HMMA.
//
// A is pre-converted ONCE to fp16 in a __device__ buffer with the fragment
// permutation baked per 32-cin granule; B prepacked fragment/lane-major.
// Mainloop per warp/slab: 4 A LDS.128 + 8 B LDS.128 -> 32 HMMA.16816.
// 3-stage cp.async pipeline (16KB/stage), one barrier per slab.

#define H_ 56
#define W_ 56
#define HW 3136
#define COUT 256
#define NSLAB 36
#define NPIX (32 * HW)          // 100352

// fp16 A image, fragment-permuted per 32-cin granule: 25.7 MB.
__device__ __half g_Ah[(size_t)NPIX * 128];
// fp16 B, fragment-major: [cout-tile][slab][4096 halves = 8KB].
__device__ __half g_Bh[2][NSLAB][4096];

static __device__ __forceinline__ uint32_t smem_u32(const void* p) {
    uint32_t a;
    asm("{ .reg .u64 t; cvta.to.shared.u64 t, %1; cvt.u32.u64 %0, t; }"
        : "=r"(a) : "l"(p));
    return a;
}
static __device__ __forceinline__ void cpasync16(uint32_t dst, const void* src, int sz) {
    asm volatile("cp.async.cg.shared.global [%0], [%1], 16, %2;"
                 :: "r"(dst), "l"(src), "r"(sz) : "memory");
}

#define MMA_F16(d, a0, a1, a2, a3, b0, b1)                                         \
    asm volatile(                                                                  \
        "mma.sync.aligned.m16n8k16.row.col.f32.f16.f16.f32 "                       \
        "{%0,%1,%2,%3}, {%4,%5,%6,%7}, {%8,%9}, {%0,%1,%2,%3};"                    \
        : "+f"((d)[0]), "+f"((d)[1]), "+f"((d)[2]), "+f"((d)[3])                   \
        : "r"(a0), "r"(a1), "r"(a2), "r"(a3), "r"(b0), "r"(b1))

// ---------------- A prepack: fp32 -> fp16 with fragment permutation ----------------
// For each 32-cin slab, physical half p (granule tig = p>>3, w = p&7) holds
// logical cin = 2*tig + (w&1) + 8*((w>>1)&1) + 16*(w>>2).
// Then one LDS.128 per (row, tig) yields regs [ks0-lo, ks0-hi, ks1-lo, ks1-hi].
__global__ void prepackA(const float* __restrict__ in) {
    const size_t slab = (size_t)blockIdx.x * 256 + threadIdx.x;   // 401408 slabs
    const float* src = in + slab * 32;
    float f[32];
    #pragma unroll
    for (int q = 0; q < 8; ++q) *(float4*)&f[q * 4] = ((const float4*)src)[q];
    __half h[32];
    #pragma unroll
    for (int p = 0; p < 32; ++p) {
        const int tig = p >> 3, w = p & 7;
        const int k = 2 * tig + (w & 1) + 8 * ((w >> 1) & 1) + 16 * (w >> 2);
        h[p] = __float2half(f[k]);
    }
    uint4* dst = (uint4*)(g_Ah + slab * 32);
    #pragma unroll
    for (int q = 0; q < 4; ++q) dst[q] = ((const uint4*)h)[q];
}

// ---------------- B prepack ----------------
// Half-index o in [0,4096): wn=o>>11, ks=(o>>10)&1, j=(o>>8)&3, lane=(o>>3)&31, e=o&7.
// g=lane>>2, tig=lane&3; nt=2*j+(e>>2); reg=(e>>1)&1; which=e&1.
// value = W[k = 2*tig + which + 8*reg + 16*ks][n = wn*64 + nt*8 + g]
__global__ void prepackB(const float* __restrict__ wgt) {
    const int s  = blockIdx.x;     // slab 0..35
    const int ct = blockIdx.y;     // cout tile 0..1
    const int t  = threadIdx.x;
    const int f  = s >> 2;         // tap
    const int cs = s & 3;          // cin slab
    __half* dst = &g_Bh[ct][s][0];
    #pragma unroll
    for (int q = 0; q < 16; ++q) {
        const int o    = t * 16 + q;
        const int wn   = o >> 11;
        const int ks   = (o >> 10) & 1;
        const int j    = (o >> 8) & 3;
        const int lane = (o >> 3) & 31;
        const int e    = o & 7;
        const int g    = lane >> 2, tig = lane & 3;
        const int nt   = 2 * j + (e >> 2);
        const int reg  = (e >> 1) & 1;
        const int k    = 2 * tig + (e & 1) + 8 * reg + 16 * ks;
        const int n    = wn * 64 + nt * 8 + g;
        dst[o] = __float2half(
            wgt[(size_t)(f * 128 + cs * 32 + k) * COUT + ct * 128 + n]);
    }
}

// ---------------- main kernel ----------------
// dyn smem: 3 stages x (A 8KB + B 8KB) = 49152 bytes.
#define SMEM_BYTES 49152

__global__ __launch_bounds__(256, 2)
void conv_mma_f16(const float* __restrict__ bias, float* __restrict__ out) {
    extern __shared__ char smem[];
    const uint32_t sb = smem_u32(smem);
    const int tid  = threadIdx.x;
    const int lane = tid & 31;
    const int wid  = tid >> 5;
    const int g    = lane >> 2;
    const int tig  = lane & 3;
    const int wm   = wid & 3;        // warp M index -> 32 rows
    const int wn   = wid >> 2;       // warp N index -> 64 cols
    const int ntCTA   = blockIdx.x;
    const int pixBase = blockIdx.y * 128;

    // A-copy ownership: thread -> pixel row (tid>>1), half (tid&1) of 64B.
    const int rowA  = tid >> 1;
    const int halfA = tid & 1;
    const int pix = pixBase + rowA;
    const int n   = pix / HW;
    const int rm  = pix - n * HW;
    const int oh  = rm / W_;
    const int ow  = rm - oh * W_;

    float acc[2][8][4];
    #pragma unroll
    for (int mt = 0; mt < 2; ++mt)
        #pragma unroll
        for (int nt = 0; nt < 8; ++nt)
            #pragma unroll
            for (int e = 0; e < 4; ++e) acc[mt][nt][e] = 0.f;

    const char* Ag = (const char*)&g_Ah[0];
    const char* Bg = (const char*)&g_Bh[ntCTA][0][0];

    auto issue_copies = [&](int s, int stage) {
        const uint32_t Ab = sb + (uint32_t)stage * 16384u;
        const uint32_t Bb = Ab + 8192u;
        const int f = s >> 2, cs = s & 3;
        const int kh = f / 3, kw = f - kh * 3;
        const int ih = oh + kh - 1, iw = ow + kw - 1;
        const bool inb = (unsigned)ih < (unsigned)H_ && (unsigned)iw < (unsigned)W_;
        const char* srcA = inb
            ? Ag + ((size_t)((n * H_ + ih) * W_ + iw) * 256 + cs * 64 + halfA * 32)
            : Ag;
        const int sz = inb ? 16 : 0;
        const uint32_t dA = Ab + (uint32_t)(rowA * 64 + halfA * 32);
        cpasync16(dA,      srcA,      sz);
        cpasync16(dA + 16, srcA + 16, sz);
        const char* srcB = Bg + (size_t)s * 8192 + tid * 32;
        const uint32_t dB = Bb + (uint32_t)tid * 32;
        cpasync16(dB,      srcB,      16);
        cpasync16(dB + 16, srcB + 16, 16);
    };

    // Prologue: slabs 0 and 1 into stages 0 and 1.
    issue_copies(0, 0);
    asm volatile("cp.async.commit_group;" ::: "memory");
    issue_copies(1, 1);
    asm volatile("cp.async.commit_group;" ::: "memory");

    const uint32_t bBase = (uint32_t)(wn * 4096 + lane * 16);

    // A row byte-bases: rows wm*32 + q*8 + g (q<2 -> mt0, q>=2 -> mt1), 64B rows.
    uint32_t aOff[4];
    #pragma unroll
    for (int q = 0; q < 4; ++q)
        aOff[q] = (uint32_t)((wm * 32 + q * 8 + g) * 64 + tig * 16);

    int stage = 0;
    #pragma unroll 1
    for (int s = 0; s < NSLAB; ++s) {
        asm volatile("cp.async.wait_group 1;" ::: "memory");
        __syncthreads();

        if (s + 2 < NSLAB) {
            int st2 = stage + 2; if (st2 >= 3) st2 -= 3;
            issue_copies(s + 2, st2);
        }
        asm volatile("cp.async.commit_group;" ::: "memory");

        const char* Abuf = smem + (size_t)stage * 16384;
        const char* Bbuf = Abuf + 8192;

        // One LDS.128 per row: regs = [ks0-klo, ks0-khi, ks1-klo, ks1-khi].
        uint4 va[4];
        #pragma unroll
        for (int q = 0; q < 4; ++q) va[q] = *(const uint4*)(Abuf + aOff[q]);

        #pragma unroll
        for (int ks = 0; ks < 2; ++ks) {
            uint32_t b[8][2];
            #pragma unroll
            for (int j = 0; j < 4; ++j) {
                const uint4 v =
                    *(const uint4*)(Bbuf + bBase + (uint32_t)(ks * 2048 + j * 512));
                b[2 * j][0]     = v.x;
                b[2 * j][1]     = v.y;
                b[2 * j + 1][0] = v.z;
                b[2 * j + 1][1] = v.w;
            }
            #pragma unroll
            for (int mt = 0; mt < 2; ++mt) {
                const uint32_t a0 = ks ? va[2 * mt].z     : va[2 * mt].x;
                const uint32_t a1 = ks ? va[2 * mt + 1].z : va[2 * mt + 1].x;
                const uint32_t a2 = ks ? va[2 * mt].w     : va[2 * mt].y;
                const uint32_t a3 = ks ? va[2 * mt + 1].w : va[2 * mt + 1].y;
                #pragma unroll
                for (int nt = 0; nt < 8; ++nt)
                    MMA_F16(acc[mt][nt], a0, a1, a2, a3, b[nt][0], b[nt][1]);
            }
        }

        ++stage; if (stage >= 3) stage = 0;
    }

    // -------- epilogue: bias + ReLU, direct float2 stores --------
    #pragma unroll
    for (int nt = 0; nt < 8; ++nt) {
        const int col = ntCTA * 128 + wn * 64 + nt * 8 + tig * 2;
        const float2 bb = *(const float2*)&bias[col];
        #pragma unroll
        for (int mt = 0; mt < 2; ++mt) {
            const int r0 = pixBase + wm * 32 + mt * 16 + g;
            float2 v0, v1;
            v0.x = fmaxf(acc[mt][nt][0] + bb.x, 0.f);
            v0.y = fmaxf(acc[mt][nt][1] + bb.y, 0.f);
            v1.x = fmaxf(acc[mt][nt][2] + bb.x, 0.f);
            v1.y = fmaxf(acc[mt][nt][3] + bb.y, 0.f);
            *(float2*)&out[(size_t)r0 * COUT + col] = v0;
            *(float2*)&out[(size_t)(r0 + 8) * COUT + col] = v1;
        }
    }
}

extern "C" void kernel_launch(void* const* d_in, const int* in_sizes, int n_in,
                              void* d_out, int out_size) {
    const float* prev_a   = (const float*)d_in[0];   // [32,56,56,128]
    const float* filter_w = (const float*)d_in[1];   // [3,3,128,256]
    const float* filter_b = (const float*)d_in[2];   // [256]
    float* out = (float*)d_out;                      // [100352,256]

    prepackA<<<NPIX * 4 / 256, 256>>>(prev_a);       // 401408 cin-slabs
    prepackB<<<dim3(NSLAB, 2), 256>>>(filter_w);

    cudaFuncSetAttribute(conv_mma_f16, cudaFuncAttributeMaxDynamicSharedMemorySize,
                         SMEM_BYTES);
    conv_mma_f16<<<dim3(2, 784), 256, SMEM_BYTES>>>(filter_b, out);
}